// round 9
// baseline (speedup 1.0000x reference)
#include <cuda_runtime.h>

// Multi-class hinge (Crammer-Singer) loss, summed over batch.
// outputs: [N, C] fp32, labels: [N] int32, out: scalar fp32.
//
// sum_{i,j != y_i} max(outputs[i,j] - outputs[i,y_i] + 1, 0)
// The j == y_i term contributes exactly 1.0: sum over all j, subtract 1/row.
//
// Single-kernel graph: CTAs accumulate into a __device__ scratch scalar;
// the last CTA to finish (ticket counter) writes the final value to d_out
// with a plain store and resets the scratch/ticket for the next graph
// replay. No prologue node (no memset / zero kernel).
//
// 2 rows per CTA, 512 threads (256 per row) — best measured kernel config.
// Ground-truth value published from the owning thread's registers via smem.

static constexpr int C_DIM    = 4096;
static constexpr int THREADS  = 512;         // 256 threads per row, 2 rows
static constexpr int TPR      = 256;         // threads per row
static constexpr int WARPS    = THREADS / 32;

__device__ float        g_scratch = 0.0f;
__device__ unsigned int g_ticket  = 0u;

__global__ __launch_bounds__(THREADS) void hinge_loss_kernel(
    const float* __restrict__ outputs,
    const int* __restrict__ labels,
    float* __restrict__ out)
{
    const int tid  = threadIdx.x;
    const int half = tid >> 8;                // 0 or 1: which row
    const int rtid = tid & (TPR - 1);         // thread index within the row
    const int row  = (blockIdx.x << 1) + half;

    const float4* rowp =
        reinterpret_cast<const float4*>(outputs + (size_t)row * C_DIM);

    // All five loads below are independent — issue together.
    const int lab = __ldg(labels + row);
    float4 v0 = rowp[rtid];
    float4 v1 = rowp[rtid + TPR];
    float4 v2 = rowp[rtid + 2 * TPR];
    float4 v3 = rowp[rtid + 3 * TPR];

    // Broadcast the ground-truth value from the owning thread's registers.
    __shared__ float sg[2];
    const int f = lab >> 2;                   // float4 index within the row
    if (rtid == (f & (TPR - 1))) {
        const int chunk = f >> 8;             // which of v0..v3
        float4 v = (chunk == 0) ? v0 : (chunk == 1) ? v1 : (chunk == 2) ? v2 : v3;
        const float* e = reinterpret_cast<const float*>(&v);
        sg[half] = e[lab & 3];
    }
    __syncthreads();
    const float t = 1.0f - sg[half];          // margin = max(o + t, 0)

    float s = 0.0f;
    s += fmaxf(v0.x + t, 0.0f); s += fmaxf(v0.y + t, 0.0f);
    s += fmaxf(v0.z + t, 0.0f); s += fmaxf(v0.w + t, 0.0f);
    s += fmaxf(v1.x + t, 0.0f); s += fmaxf(v1.y + t, 0.0f);
    s += fmaxf(v1.z + t, 0.0f); s += fmaxf(v1.w + t, 0.0f);
    s += fmaxf(v2.x + t, 0.0f); s += fmaxf(v2.y + t, 0.0f);
    s += fmaxf(v2.z + t, 0.0f); s += fmaxf(v2.w + t, 0.0f);
    s += fmaxf(v3.x + t, 0.0f); s += fmaxf(v3.y + t, 0.0f);
    s += fmaxf(v3.z + t, 0.0f); s += fmaxf(v3.w + t, 0.0f);

    // warp reduce
    #pragma unroll
    for (int o = 16; o > 0; o >>= 1)
        s += __shfl_xor_sync(0xFFFFFFFFu, s, o);

    __shared__ float ws[WARPS];
    if ((tid & 31) == 0) ws[tid >> 5] = s;
    __syncthreads();

    if (tid == 0) {
        float v = ws[0];
        #pragma unroll
        for (int w = 1; w < WARPS; w++) v += ws[w];
        // subtract the j == label contribution (exactly 1.0 per row, 2 rows)
        atomicAdd(&g_scratch, v - 2.0f);
        __threadfence();
        const unsigned int ticket = atomicAdd(&g_ticket, 1u);
        if (ticket == gridDim.x - 1) {
            // All CTAs' adds are globally visible (each fenced before its
            // ticket increment). Publish and reset for the next replay.
            out[0] = *((volatile float*)&g_scratch);
            g_scratch = 0.0f;
            g_ticket  = 0u;
            __threadfence();
        }
    }
}

extern "C" void kernel_launch(void* const* d_in, const int* in_sizes, int n_in,
                              void* d_out, int out_size) {
    const float* outputs = (const float*)d_in[0];
    const int* labels = (const int*)d_in[1];
    float* out = (float*)d_out;

    const int N = in_sizes[1];          // 16384 labels

    hinge_loss_kernel<<<N / 2, THREADS>>>(outputs, labels, out);
}

// round 10
// speedup vs baseline: 1.1066x; 1.1066x over previous
#include <cuda_runtime.h>

// Multi-class hinge (Crammer-Singer) loss, summed over batch.
// outputs: [N, C] fp32, labels: [N] int32, out: scalar fp32.
//
// sum_{i,j != y_i} max(outputs[i,j] - outputs[i,y_i] + 1, 0)
// The j == y_i term contributes exactly 1.0: sum over all j, subtract 1/row.
//
// FINAL config (best measured across 8 structural variants):
//   - one CTA per row, 16384 x 256 threads, 4 x float4 per thread
//   - ground-truth value published from the owning thread's registers via
//     smem broadcast (no dependent label->gather LDG on the critical path)
//   - default-cached loads (.cs measured neutral)
//   - tiny zero-kernel prologue (memset node and fused ticket-counter
//     epilogue both measured slower)
// Kernel is pinned at the LTS fabric cap (~6300 B/cyc, path-independent):
// ~6.6-6.7 TB/s sustained = ~41 us for the 256 MB stream.

static constexpr int C_DIM   = 4096;
static constexpr int THREADS = 256;          // 4096 / (4*256) = 4 float4 per thread

__global__ void zero_out_kernel(float* out) {
    if (threadIdx.x == 0) out[0] = 0.0f;
}

__global__ __launch_bounds__(THREADS) void hinge_loss_kernel(
    const float* __restrict__ outputs,
    const int* __restrict__ labels,
    float* __restrict__ out)
{
    const int row = blockIdx.x;
    const int tid = threadIdx.x;
    const float4* rowp =
        reinterpret_cast<const float4*>(outputs + (size_t)row * C_DIM);

    // All five loads below are independent — issue together.
    const int lab = __ldg(labels + row);
    float4 v0 = rowp[tid];
    float4 v1 = rowp[tid + THREADS];
    float4 v2 = rowp[tid + 2 * THREADS];
    float4 v3 = rowp[tid + 3 * THREADS];

    // Broadcast the ground-truth value from the owning thread's registers.
    __shared__ float sg;
    const int f = lab >> 2;                   // float4 index within the row
    if (tid == (f & (THREADS - 1))) {
        const int chunk = f >> 8;             // which of v0..v3
        float4 v = (chunk == 0) ? v0 : (chunk == 1) ? v1 : (chunk == 2) ? v2 : v3;
        const float* e = reinterpret_cast<const float*>(&v);
        sg = e[lab & 3];
    }
    __syncthreads();
    const float t = 1.0f - sg;                // margin = max(o + t, 0)

    float s = 0.0f;
    s += fmaxf(v0.x + t, 0.0f); s += fmaxf(v0.y + t, 0.0f);
    s += fmaxf(v0.z + t, 0.0f); s += fmaxf(v0.w + t, 0.0f);
    s += fmaxf(v1.x + t, 0.0f); s += fmaxf(v1.y + t, 0.0f);
    s += fmaxf(v1.z + t, 0.0f); s += fmaxf(v1.w + t, 0.0f);
    s += fmaxf(v2.x + t, 0.0f); s += fmaxf(v2.y + t, 0.0f);
    s += fmaxf(v2.z + t, 0.0f); s += fmaxf(v2.w + t, 0.0f);
    s += fmaxf(v3.x + t, 0.0f); s += fmaxf(v3.y + t, 0.0f);
    s += fmaxf(v3.z + t, 0.0f); s += fmaxf(v3.w + t, 0.0f);

    // warp reduce
    #pragma unroll
    for (int o = 16; o > 0; o >>= 1)
        s += __shfl_xor_sync(0xFFFFFFFFu, s, o);

    __shared__ float ws[THREADS / 32];
    if ((tid & 31) == 0) ws[tid >> 5] = s;
    __syncthreads();

    if (tid == 0) {
        float v = ws[0];
        #pragma unroll
        for (int w = 1; w < THREADS / 32; w++) v += ws[w];
        // subtract the j == label contribution (exactly 1.0)
        atomicAdd(out, v - 1.0f);
    }
}

extern "C" void kernel_launch(void* const* d_in, const int* in_sizes, int n_in,
                              void* d_out, int out_size) {
    const float* outputs = (const float*)d_in[0];
    const int* labels = (const int*)d_in[1];
    float* out = (float*)d_out;

    const int N = in_sizes[1];          // 16384 labels

    zero_out_kernel<<<1, 32>>>(out);
    hinge_loss_kernel<<<N, THREADS>>>(outputs, labels, out);
}